// round 13
// baseline (speedup 1.0000x reference)
#include <cuda_runtime.h>

// SPDUnVectorize: out[b,i,j] = x[b, tri(min(i,j), max(i,j))]
// tri(i,j), i<=j: i*N - i*(i-1)/2 + (j-i)
//
// R8 structure (best: 240us): TB=64 tiles, 10/batch, 256 threads,
// XOR-swizzled conflict-free smem, 4x4 register transpose, plain STG.128
// (streaming .cs stores proven harmful in R11). Only change vs R8:
// diagonal-tile loads predicated to the upper wedge (skipped smem entries
// are never consumed in phase 2), removing duplicate DRAM reads.

#define NMAT 256
#define DTRI (NMAT * (NMAT + 1) / 2)   // 32896
#define TB 64
#define NTILES 10
#define THREADS 256

__constant__ int c_tbi[NTILES] = {0,0,0,0,1,1,1,2,2,3};
__constant__ int c_tbj[NTILES] = {0,1,2,3,1,2,3,2,3,3};

__device__ __forceinline__ int sw(int r, int c4) {       // swizzled float4 index
    return r * 16 + (c4 ^ ((r >> 2) & 7));
}

__global__ void __launch_bounds__(THREADS)
spd_unvec_swz(const float* __restrict__ x, float* __restrict__ out) {
    __shared__ float4 sm[TB * 16];     // 16 KB

    const int t    = threadIdx.x;
    const int b    = blockIdx.y;
    const int tile = blockIdx.x;
    const int bi = c_tbi[tile];
    const int bj = c_tbj[tile];
    const bool diag = (bi == bj);

    const float* __restrict__ xr = x + (size_t)b * DTRI;
    float* __restrict__ o = out + (size_t)b * (NMAT * NMAT);

    // ---- phase 1: load packed tile rows (scalar, coalesced), stage smem;
    //      off-diag also writes the upper tile directly (STG.128) ----
    {
        const int c4 = t & 15;        // float4 column 0..15
        const int rg = t >> 4;        // 0..15
        #pragma unroll
        for (int k = 0; k < 4; k++) {
            const int r = rg + k * 16;
            const int i = bi * TB + r;
            const int base = i * NMAT - (i * (i - 1)) / 2 - i + bj * TB + 4 * c4;
            if (!diag) {
                float4 v;
                v.x = xr[base + 0];
                v.y = xr[base + 1];
                v.z = xr[base + 2];
                v.w = xr[base + 3];
                sm[sw(r, c4)] = v;
                *reinterpret_cast<float4*>(o + i * NMAT + bj * TB + 4 * c4) = v;
            } else if (4 * c4 + 3 >= r) {
                // upper wedge only: skip duplicate reads of lower-wedge data
                float4 v;
                v.x = xr[base + 0];
                v.y = xr[base + 1];
                v.z = xr[base + 2];
                v.w = xr[base + 3];
                sm[sw(r, c4)] = v;
            }
        }
    }
    __syncthreads();

    // ---- phase 2: 4x4 register transpose, contiguous STG.128 ----
    {
        const int rr4 = t & 15;       // source-row group (=> output col group)
        const int cg  = t >> 4;       // source float4-col (=> output row group)
        const int scol = cg ^ (rr4 & 7);

        const float4 a0 = sm[(4 * rr4 + 0) * 16 + scol];
        const float4 a1 = sm[(4 * rr4 + 1) * 16 + scol];
        const float4 a2 = sm[(4 * rr4 + 2) * 16 + scol];
        const float4 a3 = sm[(4 * rr4 + 3) * 16 + scol];

        float* __restrict__ ob = o + (size_t)(bj * TB + 4 * cg) * NMAT + bi * TB + 4 * rr4;

        if (!diag) {
            *reinterpret_cast<float4*>(ob + 0 * NMAT) = make_float4(a0.x, a1.x, a2.x, a3.x);
            *reinterpret_cast<float4*>(ob + 1 * NMAT) = make_float4(a0.y, a1.y, a2.y, a3.y);
            *reinterpret_cast<float4*>(ob + 2 * NMAT) = make_float4(a0.z, a1.z, a2.z, a3.z);
            *reinterpret_cast<float4*>(ob + 3 * NMAT) = make_float4(a0.w, a1.w, a2.w, a3.w);
        } else {
            #pragma unroll
            for (int q = 0; q < 4; q++) {
                const int row = 4 * cg + q;              // tile-local output row
                const float4 d = sm[row * 16 + (rr4 ^ ((row >> 2) & 7))];
                float tr0, tr1, tr2, tr3;
                switch (q) {
                    case 0: tr0 = a0.x; tr1 = a1.x; tr2 = a2.x; tr3 = a3.x; break;
                    case 1: tr0 = a0.y; tr1 = a1.y; tr2 = a2.y; tr3 = a3.y; break;
                    case 2: tr0 = a0.z; tr1 = a1.z; tr2 = a2.z; tr3 = a3.z; break;
                    default: tr0 = a0.w; tr1 = a1.w; tr2 = a2.w; tr3 = a3.w; break;
                }
                float4 v;
                v.x = (4 * rr4 + 0 >= row) ? d.x : tr0;
                v.y = (4 * rr4 + 1 >= row) ? d.y : tr1;
                v.z = (4 * rr4 + 2 >= row) ? d.z : tr2;
                v.w = (4 * rr4 + 3 >= row) ? d.w : tr3;
                *reinterpret_cast<float4*>(ob + q * NMAT) = v;
            }
        }
    }
}

extern "C" void kernel_launch(void* const* d_in, const int* in_sizes, int n_in,
                              void* d_out, int out_size) {
    const float* x = (const float*)d_in[0];
    float* out = (float*)d_out;

    const int B = out_size / (NMAT * NMAT);   // 4096

    dim3 grid(NTILES, B);
    spd_unvec_swz<<<grid, THREADS>>>(x, out);
}

// round 14
// speedup vs baseline: 1.3281x; 1.3281x over previous
#include <cuda_runtime.h>

// SPDUnVectorize: out[b,i,j] = x[b, tri(min(i,j), max(i,j))]
// tri(i,j), i<=j: i*N - i*(i-1)/2 + (j-i)
//
// FINAL (R8, 240.1us / DRAM 83.3% / 6.6TB/s): TB=64 tiles, all-128-bit
// stores, XOR-swizzled conflict-free smem transpose:
//  smem layout: 64 rows x 16 float4; T[r] float4-col c stored at c ^ ((r>>2)&7).
//   - phase-1 STS.128: lanes have distinct c4 -> conflict-free
//   - phase-2 LDS.128 of rows 4*rr4+k: lanes have distinct rr4 -> conflict-free
//  phase 2 transposes 4x4 blocks in registers, writes 256B-contiguous STG.128.
//  Diagonal tiles: load full rows unpredicated (in-bounds, stale lower part),
//  select direct vs transposed per element at write time.
//
// Falsified alternatives (all regressed): 8 CTAs/SM (252), TB=128 (264-322),
// __stcs stores (279), predicated diag loads (316), scalar conflict-free
// (255), row-streaming (285). The 1R:2W mixed-stream HBM ceiling here is
// ~6.6 TB/s; this kernel runs at it.

#define NMAT 256
#define DTRI (NMAT * (NMAT + 1) / 2)   // 32896
#define TB 64
#define NTILES 10
#define THREADS 256

__constant__ int c_tbi[NTILES] = {0,0,0,0,1,1,1,2,2,3};
__constant__ int c_tbj[NTILES] = {0,1,2,3,1,2,3,2,3,3};

__device__ __forceinline__ int sw(int r, int c4) {       // swizzled float4 index
    return r * 16 + (c4 ^ ((r >> 2) & 7));
}

__global__ void __launch_bounds__(THREADS)
spd_unvec_swz(const float* __restrict__ x, float* __restrict__ out) {
    __shared__ float4 sm[TB * 16];     // 16 KB, no padding needed

    const int t    = threadIdx.x;
    const int b    = blockIdx.y;
    const int tile = blockIdx.x;
    const int bi = c_tbi[tile];
    const int bj = c_tbj[tile];
    const bool diag = (bi == bj);

    const float* __restrict__ xr = x + (size_t)b * DTRI;
    float* __restrict__ o = out + (size_t)b * (NMAT * NMAT);

    // ---- phase 1: load packed tile rows (scalar, coalesced), stage smem;
    //      off-diag also writes the upper tile directly (STG.128) ----
    {
        const int c4 = t & 15;        // float4 column 0..15
        const int rg = t >> 4;        // 0..15
        #pragma unroll
        for (int k = 0; k < 4; k++) {
            const int r = rg + k * 16;
            const int i = bi * TB + r;
            const int base = i * NMAT - (i * (i - 1)) / 2 - i + bj * TB + 4 * c4;
            float4 v;
            v.x = xr[base + 0];
            v.y = xr[base + 1];
            v.z = xr[base + 2];
            v.w = xr[base + 3];
            sm[sw(r, c4)] = v;
            if (!diag)
                *reinterpret_cast<float4*>(o + i * NMAT + bj * TB + 4 * c4) = v;
        }
    }
    __syncthreads();

    // ---- phase 2: 4x4 register transpose, contiguous STG.128 ----
    {
        const int rr4 = t & 15;       // source-row group (=> output col group)
        const int cg  = t >> 4;       // source float4-col (=> output row group)
        const int scol = cg ^ (rr4 & 7);

        const float4 a0 = sm[(4 * rr4 + 0) * 16 + scol];
        const float4 a1 = sm[(4 * rr4 + 1) * 16 + scol];
        const float4 a2 = sm[(4 * rr4 + 2) * 16 + scol];
        const float4 a3 = sm[(4 * rr4 + 3) * 16 + scol];

        float4 t0 = make_float4(a0.x, a1.x, a2.x, a3.x);
        float4 t1 = make_float4(a0.y, a1.y, a2.y, a3.y);
        float4 t2 = make_float4(a0.z, a1.z, a2.z, a3.z);
        float4 t3 = make_float4(a0.w, a1.w, a2.w, a3.w);

        float* __restrict__ ob = o + (size_t)(bj * TB + 4 * cg) * NMAT + bi * TB + 4 * rr4;

        if (!diag) {
            *reinterpret_cast<float4*>(ob + 0 * NMAT) = t0;
            *reinterpret_cast<float4*>(ob + 1 * NMAT) = t1;
            *reinterpret_cast<float4*>(ob + 2 * NMAT) = t2;
            *reinterpret_cast<float4*>(ob + 3 * NMAT) = t3;
        } else {
            // direct blocks: T[4cg+q][4rr4 .. +3]
            float4 tq[4] = {t0, t1, t2, t3};
            #pragma unroll
            for (int q = 0; q < 4; q++) {
                const int row = 4 * cg + q;              // tile-local output row
                const float4 d = sm[(row) * 16 + (rr4 ^ ((row >> 2) & 7))];
                float4 v;
                v.x = (4 * rr4 + 0 >= row) ? d.x : tq[q].x;
                v.y = (4 * rr4 + 1 >= row) ? d.y : tq[q].y;
                v.z = (4 * rr4 + 2 >= row) ? d.z : tq[q].z;
                v.w = (4 * rr4 + 3 >= row) ? d.w : tq[q].w;
                *reinterpret_cast<float4*>(ob + q * NMAT) = v;
            }
        }
    }
}

extern "C" void kernel_launch(void* const* d_in, const int* in_sizes, int n_in,
                              void* d_out, int out_size) {
    const float* x = (const float*)d_in[0];
    float* out = (float*)d_out;

    const int B = out_size / (NMAT * NMAT);   // 4096

    dim3 grid(NTILES, B);
    spd_unvec_swz<<<grid, THREADS>>>(x, out);
}